// round 7
// baseline (speedup 1.0000x reference)
#include <cuda_runtime.h>
#include <cuda_fp16.h>
#include <cstdint>

#define B_   16
#define C_   256
#define SEQ_ 4096
#define NQKV 768

// ---------------- scratch (static device globals) ---------------------------
__device__ __half g_xh [(size_t)B_ * C_ * SEQ_];   // x fp16 [b][k][s]
__device__ __half g_wh [(size_t)C_ * NQKV];        // Wqkv fp16 [k][768]
__device__ __half g_woh[(size_t)C_ * C_];          // Wo fp16 [k][n]
__device__ __half g_qkv[(size_t)B_ * SEQ_ * NQKV]; // fp16 [b][s][768]

// ---------------- PTX helpers ------------------------------------------------
__device__ __forceinline__ void mma_f16(float* acc, const uint32_t* a,
                                        const uint32_t* b) {
    asm volatile(
        "mma.sync.aligned.m16n8k16.row.col.f32.f16.f16.f32 "
        "{%0,%1,%2,%3}, {%4,%5,%6,%7}, {%8,%9}, {%0,%1,%2,%3};"
        : "+f"(acc[0]), "+f"(acc[1]), "+f"(acc[2]), "+f"(acc[3])
        : "r"(a[0]), "r"(a[1]), "r"(a[2]), "r"(a[3]), "r"(b[0]), "r"(b[1]));
}
__device__ __forceinline__ void ldsm4(uint32_t* r, uint32_t addr) {
    asm volatile("ldmatrix.sync.aligned.m8n8.x4.shared.b16 {%0,%1,%2,%3}, [%4];"
        : "=r"(r[0]), "=r"(r[1]), "=r"(r[2]), "=r"(r[3]) : "r"(addr));
}
__device__ __forceinline__ void ldsm4t(uint32_t* r, uint32_t addr) {
    asm volatile("ldmatrix.sync.aligned.m8n8.x4.trans.shared.b16 {%0,%1,%2,%3}, [%4];"
        : "=r"(r[0]), "=r"(r[1]), "=r"(r[2]), "=r"(r[3]) : "r"(addr));
}
__device__ __forceinline__ void cpa16(uint32_t dst, const void* src) {
    asm volatile("cp.async.cg.shared.global [%0], [%1], 16;" :: "r"(dst), "l"(src));
}
#define CP_COMMIT()  asm volatile("cp.async.commit_group;")
#define CP_WAIT1()   asm volatile("cp.async.wait_group 1;")

// ============================================================================
// Conversion passes
// ============================================================================
__global__ void conv_f4(const float4* __restrict__ in, uint2* __restrict__ oh,
                        int n4)
{
    int i = blockIdx.x * 256 + threadIdx.x;
    if (i >= n4) return;
    float4 v = in[i];
    __half2 h01 = __floats2half2_rn(v.x, v.y);
    __half2 h23 = __floats2half2_rn(v.z, v.w);
    uint2 o;
    o.x = *(uint32_t*)&h01; o.y = *(uint32_t*)&h23;
    oh[i] = o;
}

__global__ void conv_wqkv(const float* __restrict__ wq,
                          const float* __restrict__ wkv)
{
    int idx = blockIdx.x * 256 + threadIdx.x;      // 256*768
    int k = idx / NQKV, n = idx % NQKV;
    float f = (n < 256) ? wq[k * 256 + n] : wkv[k * 512 + (n - 256)];
    g_wh[idx] = __float2half_rn(f);
}

// ============================================================================
// GEMM1 (fp16, 1-term): qkv[b,s,n] = sum_k x[b,k,s]*W[k,n] + bias[n]
//   128x128 block, BK=64, 8 warps (2x4), smem 32KB/stage x2.
// ============================================================================
__global__ __launch_bounds__(256) void gemm_qkv_mma(
    const float* __restrict__ bq, const float* __restrict__ bkv)
{
    extern __shared__ __align__(16) char smem[];
    uint32_t sb = (uint32_t)__cvta_generic_to_shared(smem);

    int b  = blockIdx.z;
    int n0 = blockIdx.x * 128;
    int s0 = blockIdx.y * 128;
    const __half* xb = g_xh + (size_t)b * C_ * SEQ_;

    int tid = threadIdx.x, warp = tid >> 5, lane = tid & 31;
    int g = lane >> 2, tg = lane & 3;
    int wm = (warp & 1) * 64, wn = (warp >> 1) * 32;

    float acc[4][4][4];
    #pragma unroll
    for (int i = 0; i < 4; i++)
        #pragma unroll
        for (int j = 0; j < 4; j++)
            #pragma unroll
            for (int q = 0; q < 4; q++) acc[i][j][q] = 0.f;

    auto fill = [&](uint32_t st, int k0) {
        #pragma unroll
        for (int i = 0; i < 4; i++) {
            int idx2 = (i << 8) + tid;
            int row = idx2 >> 4, chunk = idx2 & 15;
            uint32_t doff = row * 256 + ((chunk ^ (row & 7)) << 4);
            cpa16(st + doff, xb + (size_t)(k0 + row) * SEQ_ + s0 + chunk * 8);
            cpa16(st + 16384 + doff,
                  g_wh + (size_t)(k0 + row) * NQKV + n0 + chunk * 8);
        }
    };

    fill(sb, 0);          CP_COMMIT();
    fill(sb + 32768, 64); CP_COMMIT();

    for (int kt = 0; kt < 4; kt++) {
        CP_WAIT1();
        __syncthreads();
        uint32_t sA = sb + (kt & 1) * 32768;

        #pragma unroll
        for (int ks = 0; ks < 4; ks++) {
            int row = ks * 16 + (lane & 7) + ((lane >> 4) << 3);
            int chs = (lane >> 3) & 1;
            int rx  = row & 7;
            uint32_t rowoff = row * 256;

            uint32_t ah[4][4];
            #pragma unroll
            for (int mt = 0; mt < 4; mt++) {
                int ch = ((wm + mt * 16) >> 3) + chs;
                ldsm4t(ah[mt], sA + rowoff + ((ch ^ rx) << 4));
            }
            uint32_t bh[4][2];
            #pragma unroll
            for (int p = 0; p < 2; p++) {
                int ch = ((wn + p * 16) >> 3) + chs;
                uint32_t r[4];
                ldsm4t(r, sA + 16384 + rowoff + ((ch ^ rx) << 4));
                bh[2*p][0] = r[0];   bh[2*p][1] = r[2];
                bh[2*p+1][0] = r[1]; bh[2*p+1][1] = r[3];
            }
            #pragma unroll
            for (int mt = 0; mt < 4; mt++)
                #pragma unroll
                for (int nt = 0; nt < 4; nt++)
                    mma_f16(acc[mt][nt], ah[mt], bh[nt]);
        }
        __syncthreads();
        if (kt < 2)
            fill(sb + (kt & 1) * 32768, (kt + 2) * 64);
        CP_COMMIT();
    }

    #pragma unroll
    for (int nt = 0; nt < 4; nt++) {
        int nglob = n0 + wn + nt * 8 + 2 * tg;
        float b0 = (nglob < 256) ? bq[nglob]     : bkv[nglob - 256];
        float b1 = (nglob < 256) ? bq[nglob + 1] : bkv[nglob - 255];
        #pragma unroll
        for (int mt = 0; mt < 4; mt++) {
            int s = s0 + wm + mt * 16 + g;
            size_t r0 = ((size_t)b * SEQ_ + s) * NQKV + nglob;
            size_t r1 = r0 + (size_t)8 * NQKV;
            *(__half2*)(g_qkv + r0) =
                __floats2half2_rn(acc[mt][nt][0] + b0, acc[mt][nt][1] + b1);
            *(__half2*)(g_qkv + r1) =
                __floats2half2_rn(acc[mt][nt][2] + b0, acc[mt][nt][3] + b1);
        }
    }
}

// ============================================================================
// Fused attention + GEMM2 + transpose.
//   Block = 128 tokens x full N=256. 512 threads (16 warps, 4x4).
//   Phase 1: warp w computes attention for tokens s0+w*8..+8, writes fp16
//            results straight into the A smem tile (ldsm layout, 512B rows).
//   Phase 2: out[b,n,s] = sum_k A[s,k]*wo[k,n] + bo[n], 1-term fp16,
//            B tiles (wo) double-buffered via cp.async; transposed store.
//   smem: A 64KB @0; B stages 32KB @65536 + kbuf*32768. Total 128KB.
// ============================================================================
__global__ __launch_bounds__(512, 1) void attn_gemm_out(
    const float* __restrict__ bo, float* __restrict__ out)
{
    extern __shared__ __align__(16) char smem[];
    uint32_t sb = (uint32_t)__cvta_generic_to_shared(smem);
    const uint32_t sbB = sb + 65536;

    int b  = blockIdx.y;
    int s0 = blockIdx.x * 128;

    int tid = threadIdx.x, warp = tid >> 5, lane = tid & 31;
    int g = lane >> 2, tg = lane & 3;
    int wm = (warp & 3) * 32, wn = (warp >> 2) * 64;

    // ---- B prefetch (stages 0,1) -------------------------------------------
    auto fillB = [&](uint32_t st, int k0) {
        #pragma unroll
        for (int i = 0; i < 4; i++) {
            int idx2 = (i << 9) + tid;
            int row = idx2 >> 5, ch = idx2 & 31;
            uint32_t doff = row * 512 + ((ch ^ (row & 7)) << 4);
            cpa16(st + doff, g_woh + (size_t)(k0 + row) * C_ + ch * 8);
        }
    };
    fillB(sbB, 0);          CP_COMMIT();
    fillB(sbB + 32768, 64); CP_COMMIT();

    // ---- Phase 1: attention for this block's 128 tokens --------------------
    {
        int l = lane;
        #pragma unroll 1
        for (int i = 0; i < 8; i++) {
            int r = (warp << 3) + i;               // local token row 0..127
            const __half* base = g_qkv + ((size_t)b * SEQ_ + s0 + r) * NQKV;

            float q0[4], q1[4], k0v[4], k1v[4];
            #pragma unroll
            for (int n = 0; n < 4; n++) {
                q0[n]  = __half2float(base[n * 64 + l]);
                q1[n]  = __half2float(base[n * 64 + 32 + l]);
                k0v[n] = __half2float(base[256 + n * 64 + l]);
                k1v[n] = __half2float(base[256 + n * 64 + 32 + l]);
            }
            float s[16];
            #pragma unroll
            for (int n = 0; n < 4; n++)
                #pragma unroll
                for (int m = 0; m < 4; m++)
                    s[n * 4 + m] = q0[n] * k0v[m] + q1[n] * k1v[m];
            #pragma unroll
            for (int off = 16; off > 0; off >>= 1)
                #pragma unroll
                for (int j = 0; j < 16; j++)
                    s[j] += __shfl_xor_sync(0xffffffffu, s[j], off);

            float w[16];
            #pragma unroll
            for (int n = 0; n < 4; n++) {
                float p0 = s[n*4+0] * 0.125f, p1 = s[n*4+1] * 0.125f;
                float p2 = s[n*4+2] * 0.125f, p3 = s[n*4+3] * 0.125f;
                float mx = fmaxf(fmaxf(p0, p1), fmaxf(p2, p3));
                float e0 = __expf(p0 - mx), e1 = __expf(p1 - mx);
                float e2 = __expf(p2 - mx), e3 = __expf(p3 - mx);
                float inv = 1.0f / (e0 + e1 + e2 + e3);
                w[n*4+0] = e0 * inv; w[n*4+1] = e1 * inv;
                w[n*4+2] = e2 * inv; w[n*4+3] = e3 * inv;
            }
            float o0[4] = {0.f,0.f,0.f,0.f}, o1[4] = {0.f,0.f,0.f,0.f};
            #pragma unroll
            for (int m = 0; m < 4; m++) {
                float v0 = __half2float(base[512 + m * 64 + l]);
                float v1 = __half2float(base[512 + m * 64 + 32 + l]);
                #pragma unroll
                for (int n = 0; n < 4; n++) {
                    o0[n] += w[n * 4 + m] * v0;
                    o1[n] += w[n * 4 + m] * v1;
                }
            }
            // store into A smem tile (row r, 512B rows, swizzle ch^(r&7))
            int rx = r & 7;
            uint32_t rowbase = r * 512;
            #pragma unroll
            for (int n = 0; n < 4; n++) {
                int k0i = n * 64 + l, k1i = k0i + 32;
                uint32_t b0 = 2 * k0i, b1 = 2 * k1i;
                uint32_t a0 = rowbase + (((b0 >> 4) ^ rx) << 4) + (b0 & 15);
                uint32_t a1 = rowbase + (((b1 >> 4) ^ rx) << 4) + (b1 & 15);
                __half h0 = __float2half_rn(o0[n]);
                __half h1 = __float2half_rn(o1[n]);
                asm volatile("st.shared.u16 [%0], %1;"
                             :: "r"(sb + a0), "h"(*(uint16_t*)&h0));
                asm volatile("st.shared.u16 [%0], %1;"
                             :: "r"(sb + a1), "h"(*(uint16_t*)&h1));
            }
        }
    }

    // ---- Phase 2: GEMM over K=256, BK=64, B double-buffered -----------------
    float acc[2][8][4];
    #pragma unroll
    for (int i = 0; i < 2; i++)
        #pragma unroll
        for (int j = 0; j < 8; j++)
            #pragma unroll
            for (int q = 0; q < 4; q++) acc[i][j][q] = 0.f;

    for (int kt = 0; kt < 4; kt++) {
        CP_WAIT1();
        __syncthreads();
        uint32_t sB = sbB + (kt & 1) * 32768;

        #pragma unroll
        for (int ks = 0; ks < 4; ks++) {
            // A fragments (non-trans), full-K A tile: chunk = kt*8 + ks*2
            uint32_t ah[2][4];
            #pragma unroll
            for (int mt = 0; mt < 2; mt++) {
                int row = wm + mt * 16 + (lane & 15);
                int ch  = kt * 8 + ks * 2 + (lane >> 4);
                ldsm4(ah[mt], sb + row * 512 + ((ch ^ (row & 7)) << 4));
            }
            // B fragments (trans)
            int rowb = ks * 16 + (lane & 7) + ((lane >> 4) << 3);
            int chs  = (lane >> 3) & 1;
            int rx   = rowb & 7;
            uint32_t rowoff = rowb * 512;
            uint32_t bh[8][2];
            #pragma unroll
            for (int p = 0; p < 4; p++) {
                int ch = ((wn + p * 16) >> 3) + chs;
                uint32_t r[4];
                ldsm4t(r, sB + rowoff + ((ch ^ rx) << 4));
                bh[2*p][0] = r[0];   bh[2*p][1] = r[2];
                bh[2*p+1][0] = r[1]; bh[2*p+1][1] = r[3];
            }
            #pragma unroll
            for (int mt = 0; mt < 2; mt++)
                #pragma unroll
                for (int nt = 0; nt < 8; nt++)
                    mma_f16(acc[mt][nt], ah[mt], bh[nt]);
        }
        __syncthreads();
        if (kt < 2)
            fillB(sbB + (kt & 1) * 32768, (kt + 2) * 64);
        CP_COMMIT();
    }

    // ---- fused-transpose epilogue ------------------------------------------
    float* ob = out + (size_t)b * C_ * SEQ_;
    #pragma unroll
    for (int nt = 0; nt < 8; nt++) {
        int c = wn + nt * 8 + 2 * tg;
        float b0 = bo[c], b1 = bo[c + 1];
        #pragma unroll
        for (int mt = 0; mt < 2; mt++) {
            int s = s0 + wm + mt * 16 + g;
            ob[(size_t)c       * SEQ_ + s]     = acc[mt][nt][0] + b0;
            ob[(size_t)(c + 1) * SEQ_ + s]     = acc[mt][nt][1] + b1;
            ob[(size_t)c       * SEQ_ + s + 8] = acc[mt][nt][2] + b0;
            ob[(size_t)(c + 1) * SEQ_ + s + 8] = acc[mt][nt][3] + b1;
        }
    }
}

// ============================================================================
extern "C" void kernel_launch(void* const* d_in, const int* in_sizes, int n_in,
                              void* d_out, int out_size)
{
    const float* x   = (const float*)d_in[0];
    const float* wq  = (const float*)d_in[1];
    const float* bq  = (const float*)d_in[2];
    const float* wkv = (const float*)d_in[3];
    const float* bkv = (const float*)d_in[4];
    const float* wo  = (const float*)d_in[5];
    const float* bo  = (const float*)d_in[6];
    float* out = (float*)d_out;

    static bool attr_set = false;
    if (!attr_set) {
        cudaFuncSetAttribute(gemm_qkv_mma,
            cudaFuncAttributeMaxDynamicSharedMemorySize, 65536);
        cudaFuncSetAttribute(attn_gemm_out,
            cudaFuncAttributeMaxDynamicSharedMemorySize, 131072);
        attr_set = true;
    }

    __half *xh, *woh;
    cudaGetSymbolAddress((void**)&xh,  g_xh);
    cudaGetSymbolAddress((void**)&woh, g_woh);

    int nx4 = (B_ * C_ * SEQ_) / 4;
    conv_f4<<<(nx4 + 255) / 256, 256>>>((const float4*)x, (uint2*)xh, nx4);
    int nw4 = (C_ * C_) / 4;
    conv_f4<<<(nw4 + 255) / 256, 256>>>((const float4*)wo, (uint2*)woh, nw4);
    conv_wqkv<<<(C_ * NQKV) / 256, 256>>>(wq, wkv);

    gemm_qkv_mma<<<dim3(6, 32, 16), 256, 65536>>>(bq, bkv);
    attn_gemm_out<<<dim3(SEQ_ / 128, B_), 512, 131072>>>(bo, out);
}

// round 8
// speedup vs baseline: 1.1331x; 1.1331x over previous
#include <cuda_runtime.h>
#include <cuda_fp16.h>
#include <cstdint>

#define B_   16
#define C_   256
#define SEQ_ 4096
#define NQKV 768

// ---------------- scratch (static device globals) ---------------------------
__device__ __half g_xh [(size_t)B_ * C_ * SEQ_];   // x fp16 [b][k][s]
__device__ __half g_wh [(size_t)C_ * NQKV];        // Wqkv fp16 [k][768]
__device__ __half g_woh[(size_t)C_ * C_];          // Wo fp16 [k][n]
__device__ __half g_qkv[(size_t)B_ * SEQ_ * NQKV]; // fp16 [b][s][768]
__device__ __half g_ah [(size_t)B_ * SEQ_ * C_];   // attn out fp16 [b][s][k]

// ---------------- PTX helpers ------------------------------------------------
__device__ __forceinline__ void mma_f16(float* acc, const uint32_t* a,
                                        const uint32_t* b) {
    asm volatile(
        "mma.sync.aligned.m16n8k16.row.col.f32.f16.f16.f32 "
        "{%0,%1,%2,%3}, {%4,%5,%6,%7}, {%8,%9}, {%0,%1,%2,%3};"
        : "+f"(acc[0]), "+f"(acc[1]), "+f"(acc[2]), "+f"(acc[3])
        : "r"(a[0]), "r"(a[1]), "r"(a[2]), "r"(a[3]), "r"(b[0]), "r"(b[1]));
}
__device__ __forceinline__ void ldsm4(uint32_t* r, uint32_t addr) {
    asm volatile("ldmatrix.sync.aligned.m8n8.x4.shared.b16 {%0,%1,%2,%3}, [%4];"
        : "=r"(r[0]), "=r"(r[1]), "=r"(r[2]), "=r"(r[3]) : "r"(addr));
}
__device__ __forceinline__ void ldsm4t(uint32_t* r, uint32_t addr) {
    asm volatile("ldmatrix.sync.aligned.m8n8.x4.trans.shared.b16 {%0,%1,%2,%3}, [%4];"
        : "=r"(r[0]), "=r"(r[1]), "=r"(r[2]), "=r"(r[3]) : "r"(addr));
}
__device__ __forceinline__ void cpa16(uint32_t dst, const void* src) {
    asm volatile("cp.async.cg.shared.global [%0], [%1], 16;" :: "r"(dst), "l"(src));
}
#define CP_COMMIT()  asm volatile("cp.async.commit_group;")
#define CP_WAIT1()   asm volatile("cp.async.wait_group 1;")
#define CP_WAIT2()   asm volatile("cp.async.wait_group 2;")

// ============================================================================
// Conversion passes
// ============================================================================
__global__ void conv_f4(const float4* __restrict__ in, uint2* __restrict__ oh,
                        int n4)
{
    int i = blockIdx.x * 256 + threadIdx.x;
    if (i >= n4) return;
    float4 v = in[i];
    __half2 h01 = __floats2half2_rn(v.x, v.y);
    __half2 h23 = __floats2half2_rn(v.z, v.w);
    uint2 o;
    o.x = *(uint32_t*)&h01; o.y = *(uint32_t*)&h23;
    oh[i] = o;
}

__global__ void conv_wqkv(const float* __restrict__ wq,
                          const float* __restrict__ wkv)
{
    int idx = blockIdx.x * 256 + threadIdx.x;      // 256*768
    int k = idx / NQKV, n = idx % NQKV;
    float f = (n < 256) ? wq[k * 256 + n] : wkv[k * 512 + (n - 256)];
    g_wh[idx] = __float2half_rn(f);
}

// ============================================================================
// GEMM1 (fp16, 1-term): qkv[b,s,n] = sum_k x[b,k,s]*W[k,n] + bias[n]
//   128x128 block, BK=32, 8 warps (2x4).
//   4-stage cp.async pipeline (16KB/stage: A 8KB + B 8KB), fill issued
//   right after the stage-wait sync, BEFORE the MMAs -> LDGSTS overlaps HMMA.
// ============================================================================
#define G1_ST 16384

__global__ __launch_bounds__(256) void gemm_qkv_mma(
    const float* __restrict__ bq, const float* __restrict__ bkv)
{
    extern __shared__ __align__(16) char smem[];
    uint32_t sb = (uint32_t)__cvta_generic_to_shared(smem);

    int b  = blockIdx.z;
    int n0 = blockIdx.x * 128;
    int s0 = blockIdx.y * 128;
    const __half* xb = g_xh + (size_t)b * C_ * SEQ_;

    int tid = threadIdx.x, warp = tid >> 5, lane = tid & 31;
    int g = lane >> 2, tg = lane & 3;
    int wm = (warp & 1) * 64, wn = (warp >> 1) * 32;

    float acc[4][4][4];
    #pragma unroll
    for (int i = 0; i < 4; i++)
        #pragma unroll
        for (int j = 0; j < 4; j++)
            #pragma unroll
            for (int q = 0; q < 4; q++) acc[i][j][q] = 0.f;

    // stage fill: 32 rows(k) x 128 cols, 256B rows, 16 chunks, swz ch^(row&7)
    auto fill = [&](uint32_t st, int kt) {
        int k0 = kt * 32;
        #pragma unroll
        for (int i = 0; i < 2; i++) {
            int idx2 = (i << 8) + tid;
            int row = idx2 >> 4, ch = idx2 & 15;
            uint32_t doff = row * 256 + ((ch ^ (row & 7)) << 4);
            cpa16(st + doff, xb + (size_t)(k0 + row) * SEQ_ + s0 + ch * 8);
            cpa16(st + 8192 + doff,
                  g_wh + (size_t)(k0 + row) * NQKV + n0 + ch * 8);
        }
    };

    fill(sb,              0); CP_COMMIT();
    fill(sb + G1_ST,      1); CP_COMMIT();
    fill(sb + 2 * G1_ST,  2); CP_COMMIT();

    for (int kt = 0; kt < 8; kt++) {
        CP_WAIT2();
        __syncthreads();
        // refill the buffer consumed at kt-1 with k-tile kt+3 (overlaps MMAs)
        if (kt < 5) fill(sb + ((kt + 3) & 3) * G1_ST, kt + 3);
        CP_COMMIT();

        uint32_t sA = sb + (kt & 3) * G1_ST;
        #pragma unroll
        for (int ks = 0; ks < 2; ks++) {
            int row = ks * 16 + (lane & 7) + ((lane >> 4) << 3);
            int chs = (lane >> 3) & 1;
            int rx  = row & 7;
            uint32_t rowoff = row * 256;

            uint32_t ah[4][4];
            #pragma unroll
            for (int mt = 0; mt < 4; mt++) {
                int ch = ((wm + mt * 16) >> 3) + chs;
                ldsm4t(ah[mt], sA + rowoff + ((ch ^ rx) << 4));
            }
            uint32_t bh[4][2];
            #pragma unroll
            for (int p = 0; p < 2; p++) {
                int ch = ((wn + p * 16) >> 3) + chs;
                uint32_t r[4];
                ldsm4t(r, sA + 8192 + rowoff + ((ch ^ rx) << 4));
                bh[2*p][0] = r[0];   bh[2*p][1] = r[2];
                bh[2*p+1][0] = r[1]; bh[2*p+1][1] = r[3];
            }
            #pragma unroll
            for (int mt = 0; mt < 4; mt++)
                #pragma unroll
                for (int nt = 0; nt < 4; nt++)
                    mma_f16(acc[mt][nt], ah[mt], bh[nt]);
        }
    }

    #pragma unroll
    for (int nt = 0; nt < 4; nt++) {
        int nglob = n0 + wn + nt * 8 + 2 * tg;
        float b0 = (nglob < 256) ? bq[nglob]     : bkv[nglob - 256];
        float b1 = (nglob < 256) ? bq[nglob + 1] : bkv[nglob - 255];
        #pragma unroll
        for (int mt = 0; mt < 4; mt++) {
            int s = s0 + wm + mt * 16 + g;
            size_t r0 = ((size_t)b * SEQ_ + s) * NQKV + nglob;
            size_t r1 = r0 + (size_t)8 * NQKV;
            *(__half2*)(g_qkv + r0) =
                __floats2half2_rn(acc[mt][nt][0] + b0, acc[mt][nt][1] + b1);
            *(__half2*)(g_qkv + r1) =
                __floats2half2_rn(acc[mt][nt][2] + b0, acc[mt][nt][3] + b1);
        }
    }
}

// ============================================================================
// Attention: per token, 4x4 over heads. One warp per token. fp16 in/out.
// ============================================================================
__global__ __launch_bounds__(256) void attn_kernel()
{
    int warp = threadIdx.x >> 5, l = threadIdx.x & 31;
    int t = blockIdx.x * 8 + warp;
    const __half* base = g_qkv + (size_t)t * NQKV;

    float q0[4], q1[4], k0v[4], k1v[4];
    #pragma unroll
    for (int n = 0; n < 4; n++) {
        q0[n]  = __half2float(base[n * 64 + l]);
        q1[n]  = __half2float(base[n * 64 + 32 + l]);
        k0v[n] = __half2float(base[256 + n * 64 + l]);
        k1v[n] = __half2float(base[256 + n * 64 + 32 + l]);
    }
    float s[16];
    #pragma unroll
    for (int n = 0; n < 4; n++)
        #pragma unroll
        for (int m = 0; m < 4; m++)
            s[n * 4 + m] = q0[n] * k0v[m] + q1[n] * k1v[m];
    #pragma unroll
    for (int off = 16; off > 0; off >>= 1)
        #pragma unroll
        for (int i = 0; i < 16; i++)
            s[i] += __shfl_xor_sync(0xffffffffu, s[i], off);

    float w[16];
    #pragma unroll
    for (int n = 0; n < 4; n++) {
        float p0 = s[n*4+0] * 0.125f, p1 = s[n*4+1] * 0.125f;
        float p2 = s[n*4+2] * 0.125f, p3 = s[n*4+3] * 0.125f;
        float mx = fmaxf(fmaxf(p0, p1), fmaxf(p2, p3));
        float e0 = __expf(p0 - mx), e1 = __expf(p1 - mx);
        float e2 = __expf(p2 - mx), e3 = __expf(p3 - mx);
        float inv = 1.0f / (e0 + e1 + e2 + e3);
        w[n*4+0] = e0 * inv; w[n*4+1] = e1 * inv;
        w[n*4+2] = e2 * inv; w[n*4+3] = e3 * inv;
    }
    float o0[4] = {0.f,0.f,0.f,0.f}, o1[4] = {0.f,0.f,0.f,0.f};
    #pragma unroll
    for (int m = 0; m < 4; m++) {
        float v0 = __half2float(base[512 + m * 64 + l]);
        float v1 = __half2float(base[512 + m * 64 + 32 + l]);
        #pragma unroll
        for (int n = 0; n < 4; n++) {
            o0[n] += w[n * 4 + m] * v0;
            o1[n] += w[n * 4 + m] * v1;
        }
    }
    size_t d = (size_t)t * C_;
    #pragma unroll
    for (int n = 0; n < 4; n++) {
        g_ah[d + n * 64 + l]      = __float2half_rn(o0[n]);
        g_ah[d + n * 64 + 32 + l] = __float2half_rn(o1[n]);
    }
}

// ============================================================================
// GEMM2 (fp16, 1-term, fused transpose): out[b,n,s] = sum_k attn[b,s,k]*wo[k,n]+bo[n]
//   A = attn fp16 [s][k] -> row-major tile (128B rows), ldmatrix non-trans
//   B = wo fp16 [k][n]   -> trans tile (256B rows)
//   128x128 block, BK=64, 2 stages x 32KB (A 16KB @0, B 16KB @16384).
// ============================================================================
__global__ __launch_bounds__(256) void gemm_out_mma(
    const float* __restrict__ bo, float* __restrict__ out)
{
    extern __shared__ __align__(16) char smem[];
    uint32_t sb = (uint32_t)__cvta_generic_to_shared(smem);

    int b  = blockIdx.z;
    int n0 = blockIdx.x * 128;
    int s0 = blockIdx.y * 128;
    const __half* ah_b = g_ah + (size_t)b * SEQ_ * C_;

    int tid = threadIdx.x, warp = tid >> 5, lane = tid & 31;
    int g = lane >> 2, tg = lane & 3;
    int wm = (warp & 1) * 64, wn = (warp >> 1) * 32;

    float acc[4][4][4];
    #pragma unroll
    for (int i = 0; i < 4; i++)
        #pragma unroll
        for (int j = 0; j < 4; j++)
            #pragma unroll
            for (int q = 0; q < 4; q++) acc[i][j][q] = 0.f;

    auto fill = [&](uint32_t st, int k0) {
        #pragma unroll
        for (int i = 0; i < 4; i++) {
            int idx2 = (i << 8) + tid;
            // A: 128 rows(s) x 64 k, 128B rows, 8 chunks, swz ch^(row&7)
            int rowA = idx2 >> 3, chA = idx2 & 7;
            uint32_t dA = rowA * 128 + ((chA ^ (rowA & 7)) << 4);
            cpa16(st + dA, ah_b + (size_t)(s0 + rowA) * C_ + k0 + chA * 8);
            // B: 64 rows(k) x 128 cols(n), 256B rows, 16 chunks, swz ch^(row&7)
            int rowB = idx2 >> 4, chB = idx2 & 15;
            uint32_t dB = rowB * 256 + ((chB ^ (rowB & 7)) << 4);
            cpa16(st + 16384 + dB,
                  g_woh + (size_t)(k0 + rowB) * C_ + n0 + chB * 8);
        }
    };

    fill(sb, 0);          CP_COMMIT();
    fill(sb + 32768, 64); CP_COMMIT();

    for (int kt = 0; kt < 4; kt++) {
        CP_WAIT1();
        __syncthreads();
        uint32_t sA = sb + (kt & 1) * 32768;
        uint32_t sB = sA + 16384;

        #pragma unroll
        for (int ks = 0; ks < 4; ks++) {
            uint32_t ah[4][4];
            #pragma unroll
            for (int mt = 0; mt < 4; mt++) {
                int row = wm + mt * 16 + (lane & 15);
                int ch  = ks * 2 + (lane >> 4);
                ldsm4(ah[mt], sA + row * 128 + ((ch ^ (row & 7)) << 4));
            }
            int rowb = ks * 16 + (lane & 7) + ((lane >> 4) << 3);
            int chs  = (lane >> 3) & 1;
            int rx   = rowb & 7;
            uint32_t rowoff = rowb * 256;
            uint32_t bh[4][2];
            #pragma unroll
            for (int p = 0; p < 2; p++) {
                int ch = ((wn + p * 16) >> 3) + chs;
                uint32_t r[4];
                ldsm4t(r, sB + rowoff + ((ch ^ rx) << 4));
                bh[2*p][0] = r[0];   bh[2*p][1] = r[2];
                bh[2*p+1][0] = r[1]; bh[2*p+1][1] = r[3];
            }
            #pragma unroll
            for (int mt = 0; mt < 4; mt++)
                #pragma unroll
                for (int nt = 0; nt < 4; nt++)
                    mma_f16(acc[mt][nt], ah[mt], bh[nt]);
        }
        __syncthreads();
        if (kt < 2)
            fill(sb + (kt & 1) * 32768, (kt + 2) * 64);
        CP_COMMIT();
    }

    // fused-transpose epilogue
    float* ob = out + (size_t)b * C_ * SEQ_;
    #pragma unroll
    for (int nt = 0; nt < 4; nt++) {
        int c = n0 + wn + nt * 8 + 2 * tg;
        float b0 = bo[c], b1 = bo[c + 1];
        #pragma unroll
        for (int mt = 0; mt < 4; mt++) {
            int s = s0 + wm + mt * 16 + g;
            ob[(size_t)c       * SEQ_ + s]     = acc[mt][nt][0] + b0;
            ob[(size_t)(c + 1) * SEQ_ + s]     = acc[mt][nt][1] + b1;
            ob[(size_t)c       * SEQ_ + s + 8] = acc[mt][nt][2] + b0;
            ob[(size_t)(c + 1) * SEQ_ + s + 8] = acc[mt][nt][3] + b1;
        }
    }
}

// ============================================================================
extern "C" void kernel_launch(void* const* d_in, const int* in_sizes, int n_in,
                              void* d_out, int out_size)
{
    const float* x   = (const float*)d_in[0];
    const float* wq  = (const float*)d_in[1];
    const float* bq  = (const float*)d_in[2];
    const float* wkv = (const float*)d_in[3];
    const float* bkv = (const float*)d_in[4];
    const float* wo  = (const float*)d_in[5];
    const float* bo  = (const float*)d_in[6];
    float* out = (float*)d_out;

    static bool attr_set = false;
    if (!attr_set) {
        cudaFuncSetAttribute(gemm_qkv_mma,
            cudaFuncAttributeMaxDynamicSharedMemorySize, 65536);
        cudaFuncSetAttribute(gemm_out_mma,
            cudaFuncAttributeMaxDynamicSharedMemorySize, 65536);
        attr_set = true;
    }

    __half *xh, *woh;
    cudaGetSymbolAddress((void**)&xh,  g_xh);
    cudaGetSymbolAddress((void**)&woh, g_woh);

    int nx4 = (B_ * C_ * SEQ_) / 4;
    conv_f4<<<(nx4 + 255) / 256, 256>>>((const float4*)x, (uint2*)xh, nx4);
    int nw4 = (C_ * C_) / 4;
    conv_f4<<<(nw4 + 255) / 256, 256>>>((const float4*)wo, (uint2*)woh, nw4);
    conv_wqkv<<<(C_ * NQKV) / 256, 256>>>(wq, wkv);

    gemm_qkv_mma<<<dim3(6, 32, 16), 256, 65536>>>(bq, bkv);
    attn_kernel<<<(B_ * SEQ_) / 8, 256>>>();
    gemm_out_mma<<<dim3(2, 32, 16), 256, 65536>>>(bo, out);
}